// round 15
// baseline (speedup 1.0000x reference)
#include <cuda_runtime.h>
#include <cuda_fp16.h>
#include <cstdint>

#define B_ 32
#define C_ 256
#define H_ 32
#define W_ 32
#define K_ 1024
#define N_ 1024
#define I_ 256
#define ZELEMS (B_*C_*H_*W_)   /* 8388608 */
#define NPOS   (B_*N_)         /* 32768   */

#define EPS_CAND 0.004f
#define CMAX 16

// ---------------- scratch ----------------
__device__ float  g_zz[B_][I_][N_];     // 32 MB exact reinterpreted view [b][i][n]
__device__ __half2 g_zh[B_][I_][N_/2];  // 16 MB fp16 z pairs over adjacent n
__device__ __half2 g_ehd[I_][K_];       // 1 MB duplicated fp16 emb: {e,e}
__device__ float  g_t[NPOS];
__device__ float  g_s[K_];
__device__ float          g_cd[NPOS*8*CMAX];
__device__ unsigned short g_ck[NPOS*8*CMAX];
__device__ int            g_ccnt[NPOS*8];
__device__ int    g_idx[NPOS];
__device__ double g_lacc;

__global__ void k_init() { g_lacc = 0.0; }
__global__ __launch_bounds__(256) void k_zero() {
    int i = blockIdx.x*256 + threadIdx.x;
    if (i < NPOS*8) g_ccnt[i] = 0;
}

__device__ __forceinline__ uint32_t smem_u32(const void* p) {
    uint32_t a;
    asm("{ .reg .u64 t; cvta.to.shared.u64 t, %1; cvt.u32.u64 %0, t; }" : "=r"(a) : "l"(p));
    return a;
}
__device__ __forceinline__ void cp16(uint32_t dst, const void* src) {
    asm volatile("cp.async.cg.shared.global [%0], [%1], 16;" :: "r"(dst), "l"(src));
}

// ---------------- transpose: z -> g_zz (exact fp32) + g_zh (fp16 n-pairs) ----------------
// zz[b,i,n] = z[b, n&255, i>>3, 4*(i&7)+(n>>8)]
__global__ __launch_bounds__(256) void k_transpose(const float* __restrict__ z) {
    __shared__ float tile[64][33];
    int c0 = blockIdx.x * 64;
    int h  = blockIdx.y;
    int b  = blockIdx.z;
    int t  = threadIdx.x;
    for (int e = t; e < 2048; e += 256) {
        int row = e >> 5, w = e & 31;
        tile[row][w] = z[(((b*C_) + c0 + row)*H_ + h)*W_ + w];
    }
    __syncthreads();
    for (int e = t; e < 2048; e += 256) {
        int cc = e & 63, chunk = e >> 6;
        int il = chunk >> 2, q = chunk & 3;
        g_zz[b][h*8 + il][q*256 + c0 + cc] = tile[cc][il*4 + q];
    }
    for (int e = t; e < 1024; e += 256) {
        int c2 = e >> 5, wq = e & 31;
        int il = wq >> 2, q = wq & 3;
        int c = c2*2;
        float v0 = tile[c][il*4 + q];
        float v1 = tile[c+1][il*4 + q];
        int n = q*256 + c0 + c;
        g_zh[b][h*8 + il][n >> 1] = __floats2half2_rn(v0, v1);
    }
}

__global__ __launch_bounds__(256) void k_eh(const float* __restrict__ emb) {
    int gid = blockIdx.x*256 + threadIdx.x;
    int i = gid >> 10, k = gid & 1023;
    float v = emb[k*256 + i];
    g_ehd[i][k] = __floats2half2_rn(v, v);
}

__global__ __launch_bounds__(256) void k_tn() {
    int gn = blockIdx.x*blockDim.x + threadIdx.x;
    if (gn >= NPOS) return;
    int b = gn >> 10, n = gn & 1023;
    float acc = 0.f;
    for (int i = 0; i < I_; ++i) {
        float v = g_zz[b][i][n];
        acc = __fadd_rn(acc, __fmul_rn(v, v));
    }
    g_t[gn] = acc;
}

__global__ __launch_bounds__(256) void k_sk(const float* __restrict__ emb) {
    __shared__ float sm[64*257];
    int k0 = blockIdx.x*64;
    int t = threadIdx.x;
    for (int j = 0; j < 64; ++j)
        sm[j*257 + t] = emb[(k0+j)*256 + t];
    __syncthreads();
    if (t < 64) {
        float acc = 0.f;
        for (int c = 0; c < 256; ++c) {
            float v = sm[t*257 + c];
            acc = __fadd_rn(acc, __fmul_rn(v, v));
        }
        g_s[k0 + t] = acc;
    }
}

// ---------------- HFMA2 screen v2: deep tile + cp.async double buffer ----------------
// grid (nb=4, kb=8, b=32), 256 thr. CTA tile 128k x 256n x 256i (8 panels of 32 i).
// Thread tile 8k x 16n (tx = n-group 0..15, ty = k-group 0..15).
// smem words: ES0[0,4096) ZS0[4096,8192) ES1[8192,12288) ZS1[12288,16384)
// Zs swizzle: uint4 u4 -> slot ((u4&1)<<4)|(u4>>1)  (Zlo/Zhi halves, conflict-free bw loads)
#define SM_TOT 65536

__global__ __launch_bounds__(256, 2) void k_screen() {
    extern __shared__ char smraw[];
    uint32_t sb = smem_u32(smraw);
    int nb = blockIdx.x, kb = blockIdx.y, b = blockIdx.z;
    int n0 = nb*256, k0 = kb*128;
    int t = threadIdx.x;
    int tx = t & 15, ty = t >> 4;

    // stage panel 'it' into buffer 'buf' (0/1)
    auto stage = [&](int it, int buf) {
        int ebase = buf ? 8192 : 0;
        int zbase = ebase + 4096;
        #pragma unroll
        for (int j = 0; j < 4; ++j) {
            int idx = j*256 + t;
            int ii = idx >> 5, u4 = idx & 31;
            cp16(sb + (uint32_t)(ebase + ii*128 + u4*4)*4,
                 &g_ehd[it*32 + ii][k0 + u4*4]);
            int slot = ((u4 & 1) << 4) | (u4 >> 1);
            cp16(sb + (uint32_t)(zbase + ii*128 + slot*4)*4,
                 &g_zh[b][it*32 + ii][(n0 >> 1) + u4*4]);
        }
        asm volatile("cp.async.commit_group;" ::: "memory");
    };

    __half2 acc[8][8];
    #pragma unroll
    for (int r = 0; r < 8; ++r)
        #pragma unroll
        for (int c = 0; c < 8; ++c) acc[r][c] = __floats2half2_rn(0.f, 0.f);

    stage(0, 0);
    for (int it = 0; it < 8; ++it) {
        if (it < 7) stage(it + 1, (it + 1) & 1);
        if (it < 7) asm volatile("cp.async.wait_group 1;" ::: "memory");
        else        asm volatile("cp.async.wait_group 0;" ::: "memory");
        __syncthreads();
        int ebase = (it & 1) ? 8192 : 0;
        int zbase = ebase + 4096;
        const char* Eb = smraw + ebase*4;
        const char* Zb = smraw + zbase*4;
        #pragma unroll 8
        for (int ii = 0; ii < 32; ++ii) {
            unsigned int a[8], bw[8];
            *(uint4*)&a[0]  = *(const uint4*)(Eb + (ii*128 + ty*8)*4);
            *(uint4*)&a[4]  = *(const uint4*)(Eb + (ii*128 + ty*8 + 4)*4);
            *(uint4*)&bw[0] = *(const uint4*)(Zb + (ii*128 + tx*4)*4);
            *(uint4*)&bw[4] = *(const uint4*)(Zb + (ii*128 + 64 + tx*4)*4);
            #pragma unroll
            for (int r = 0; r < 8; ++r)
                #pragma unroll
                for (int c = 0; c < 8; ++c)
                    acc[r][c] = __hfma2(*(__half2*)&a[r], *(__half2*)&bw[c], acc[r][c]);
        }
        __syncthreads();
    }

    // ---- epilogue: per-n tile min via smem reduce, then threshold append ----
    float* red  = (float*)smraw;            // red[ty][257], 16 rows (overlays dead buffers)
    float* tmin = (float*)smraw + 16*257;   // tmin[256]

    float sv[8], tv[16];
    #pragma unroll
    for (int r = 0; r < 8; ++r) sv[r] = g_s[k0 + ty*8 + r];
    #pragma unroll
    for (int j = 0; j < 16; ++j) tv[j] = g_t[b*1024 + n0 + tx*16 + j];

    #pragma unroll
    for (int c = 0; c < 8; ++c) {
        float m0 = __int_as_float(0x7f800000), m1 = m0;
        #pragma unroll
        for (int r = 0; r < 8; ++r) {
            float2 d2 = __half22float2(acc[r][c]);
            m0 = fminf(m0, sv[r] + tv[2*c]   - 2.0f*d2.x);
            m1 = fminf(m1, sv[r] + tv[2*c+1] - 2.0f*d2.y);
        }
        red[ty*257 + tx*16 + 2*c]     = m0;
        red[ty*257 + tx*16 + 2*c + 1] = m1;
    }
    __syncthreads();
    {
        float best = red[t];
        #pragma unroll
        for (int y = 1; y < 16; ++y) best = fminf(best, red[y*257 + t]);
        tmin[t] = best;
    }
    __syncthreads();

    #pragma unroll
    for (int c = 0; c < 8; ++c) {
        float thr0 = tmin[tx*16 + 2*c]     + EPS_CAND;
        float thr1 = tmin[tx*16 + 2*c + 1] + EPS_CAND;
        #pragma unroll
        for (int r = 0; r < 8; ++r) {
            float2 d2 = __half22float2(acc[r][c]);
            float d0 = sv[r] + tv[2*c]   - 2.0f*d2.x;
            float d1 = sv[r] + tv[2*c+1] - 2.0f*d2.y;
            if (d0 <= thr0) {
                int slot = (b*1024 + n0 + tx*16 + 2*c)*8 + kb;
                int pos = atomicAdd(&g_ccnt[slot], 1);
                if (pos < CMAX) {
                    g_cd[slot*CMAX + pos] = d0;
                    g_ck[slot*CMAX + pos] = (unsigned short)(k0 + ty*8 + r);
                }
            }
            if (d1 <= thr1) {
                int slot = (b*1024 + n0 + tx*16 + 2*c + 1)*8 + kb;
                int pos = atomicAdd(&g_ccnt[slot], 1);
                if (pos < CMAX) {
                    g_cd[slot*CMAX + pos] = d1;
                    g_ck[slot*CMAX + pos] = (unsigned short)(k0 + ty*8 + r);
                }
            }
        }
    }
}

// ---------------- exact recheck (bitwise round-1 selection chain) ----------------
__global__ __launch_bounds__(128) void k_recheck(const float* __restrict__ emb,
                                                 float* __restrict__ out, int out_size) {
    int gn = blockIdx.x*128 + threadIdx.x;
    int b = gn >> 10, n = gn & 1023;
    float tn = g_t[gn];

    float cd[8*CMAX]; unsigned short ck[8*CMAX];
    int total = 0;
    bool ovf = false;
    for (int kb = 0; kb < 8; ++kb) {
        int slot = gn*8 + kb;
        int c = g_ccnt[slot];
        if (c > CMAX) { ovf = true; continue; }
        for (int j = 0; j < c; ++j) {
            cd[total] = g_cd[slot*CMAX + j];
            ck[total] = g_ck[slot*CMAX + j];
            total++;
        }
    }

    float best = __int_as_float(0x7f800000);
    int bi = 0x7fffffff;
    if (!ovf) {
        float gmin = __int_as_float(0x7f800000);
        for (int c = 0; c < total; ++c) gmin = fminf(gmin, cd[c]);
        float thr = gmin + EPS_CAND;
        for (int c = 0; c < total; ++c) {
            if (cd[c] > thr) continue;
            int k = ck[c];
            const float* e = emb + k*256;
            float acc = 0.f;
            for (int i = 0; i < I_; ++i)
                acc = fmaf(e[i], g_zz[b][i][n], acc);
            float d = __fsub_rn(__fadd_rn(g_s[k], tn), __fmul_rn(2.0f, acc));
            if (d < best || (d == best && k < bi)) { best = d; bi = k; }
        }
    } else {
        for (int k = 0; k < K_; ++k) {
            const float* e = emb + k*256;
            float acc = 0.f;
            for (int i = 0; i < I_; ++i)
                acc = fmaf(e[i], g_zz[b][i][n], acc);
            float d = __fsub_rn(__fadd_rn(g_s[k], tn), __fmul_rn(2.0f, acc));
            if (d < best) { best = d; bi = k; }
        }
    }
    g_idx[gn] = bi;
    if (out_size >= ZELEMS + NPOS)      out[ZELEMS + gn] = (float)bi;
    else if (out_size == NPOS)          out[gn]          = (float)bi;
}

// ---------------- writeout + loss ----------------
__global__ __launch_bounds__(256) void k_writeout(const float* __restrict__ z,
                                                  const float* __restrict__ emb,
                                                  float* __restrict__ out, int out_size) {
    int o4 = blockIdx.x*256 + threadIdx.x;
    double local = 0.0;
    if (o4*4 < ZELEMS) {
        int o = o4*4;
        int w = o & 31, h = (o >> 5) & 31, c = (o >> 10) & 255, b = o >> 18;
        float4 zp4 = *(const float4*)&z[o];
        float r[4];
        float zp[4] = {zp4.x, zp4.y, zp4.z, zp4.w};
        #pragma unroll
        for (int j = 0; j < 4; ++j) {
            int n = h*32 + (w + j);
            int kidx = g_idx[b*1024 + n];
            float zq = emb[kidx*256 + c];
            float diff = __fsub_rn(zq, zp[j]);
            r[j] = __fadd_rn(zp[j], diff);
            float sq = __fmul_rn(diff, diff);
            local += (double)sq;
        }
        if (out_size >= ZELEMS) *(float4*)&out[o] = make_float4(r[0], r[1], r[2], r[3]);
    }
    __shared__ double sd[256];
    sd[threadIdx.x] = local;
    __syncthreads();
    for (int s = 128; s > 0; s >>= 1) {
        if (threadIdx.x < s) sd[threadIdx.x] += sd[threadIdx.x + s];
        __syncthreads();
    }
    if (threadIdx.x == 0) atomicAdd(&g_lacc, sd[0]);
}

__global__ void k_finalize(float* __restrict__ out, int out_size) {
    float m = (float)(g_lacc / (double)ZELEMS);
    float loss = __fadd_rn(m, __fmul_rn(0.25f, m));
    if (out_size >= ZELEMS + NPOS + 1)  out[ZELEMS + NPOS] = loss;
    else if (out_size == ZELEMS + 1)    out[ZELEMS]        = loss;
    else if (out_size == 1)             out[0]             = loss;
}

extern "C" void kernel_launch(void* const* d_in, const int* in_sizes, int n_in,
                              void* d_out, int out_size) {
    const float* z   = (const float*)d_in[0];
    const float* emb = (const float*)d_in[1];
    if (n_in >= 2 && in_sizes[0] == K_*C_ && in_sizes[1] == ZELEMS) {
        z = (const float*)d_in[1]; emb = (const float*)d_in[0];
    }
    float* out = (float*)d_out;

    cudaFuncSetAttribute(k_screen, cudaFuncAttributeMaxDynamicSharedMemorySize, SM_TOT);

    k_init<<<1, 1>>>();
    k_zero<<<NPOS*8/256, 256>>>();
    k_transpose<<<dim3(4, 32, 32), 256>>>(z);
    k_eh<<<I_*K_/256, 256>>>(emb);
    k_tn<<<NPOS/256, 256>>>();
    k_sk<<<K_/64, 256>>>(emb);
    k_screen<<<dim3(4, 8, 32), 256, SM_TOT>>>();
    k_recheck<<<NPOS/128, 128>>>(emb, out, out_size);
    k_writeout<<<ZELEMS/4/256, 256>>>(z, emb, out, out_size);
    k_finalize<<<1, 1>>>(out, out_size);
}